// round 10
// baseline (speedup 1.0000x reference)
#include <cuda_runtime.h>
#include <cuda_bf16.h>
#include <math.h>
#include <stdint.h>

// Problem constants
#define NROWS 8192
#define DIMS  256
#define NT    64                     // 8192 / 128 tiles per side
#define NPAIR (NT * (NT + 1) / 2)    // 2080 upper-triangular tiles
#define EPS_F 1e-8f

// Tiling
#define BM 128
#define BK 32
#define NCHUNK (DIMS / BK)           // 8
#define NSTAGE 3
#define STAGE_ELEMS (2 * BM * BK)    // A + B per stage, bf16 elems (8192)
#define SMEM_BYTES (NSTAGE * STAGE_ELEMS * 2)   // 49152

// Scratch (static device globals: allocation-free)
__device__ __nv_bfloat16 g_z1nb[NROWS * DIMS];  // normalized z1, row-major bf16
__device__ float  g_sq[NROWS];                  // fp32 |row|^2 after normalize
__device__ double g_pos;                        // sum of s_pos
__device__ double g_neg;                        // off-diagonal exp-sum

// ---------------------------------------------------------------------------
// helpers
// ---------------------------------------------------------------------------
__device__ __forceinline__ float block_sum_256(float v, float* sbuf) {
    #pragma unroll
    for (int o = 16; o > 0; o >>= 1)
        v += __shfl_xor_sync(0xffffffffu, v, o);
    int w = threadIdx.x >> 5;
    if ((threadIdx.x & 31) == 0) sbuf[w] = v;
    __syncthreads();
    float s = 0.f;
    #pragma unroll
    for (int i = 0; i < 8; ++i) s += sbuf[i];
    __syncthreads();
    return s;
}

// SMEM tile layout: row-major 128 x 32 bf16 (64B rows), XOR swizzle on 16B
// atoms; conflict-free for ldmatrix 8-row phases and cp.async 16B stores.
// (identical to the validated R3 kernel)
__device__ __forceinline__ int swz(int r, int atom) {
    return r * 32 + ((atom ^ ((r >> 1) & 3)) << 3);
}

// ---------------------------------------------------------------------------
__global__ void zero_kernel() { g_neg = 0.0; g_pos = 0.0; }

// ---------------------------------------------------------------------------
// prep: normalize rows, emit bf16 z1n (row-major), sq; accumulate s_pos sum
// grid = NROWS blocks, 256 threads (== DIMS)
// ---------------------------------------------------------------------------
__global__ void prep_kernel(const float* __restrict__ z1,
                            const float* __restrict__ z2) {
    __shared__ float sbuf[8];
    int i = blockIdx.x;
    int t = threadIdx.x;

    float a = z1[i * DIMS + t];
    float b = z2[i * DIMS + t];

    float s1 = block_sum_256(a * a, sbuf);
    float s2 = block_sum_256(b * b, sbuf);

    float m1 = fmaxf(sqrtf(s1), 1e-12f);
    float m2 = fmaxf(sqrtf(s2), 1e-12f);
    float an = a / m1;
    float bn = b / m2;

    g_z1nb[i * DIMS + t] = __float2bfloat16(an);

    float dpos = block_sum_256((an - bn) * (an - bn), sbuf);

    if (t == 0) {
        g_sq[i] = s1 / (m1 * m1);
        float sp = logf(__expf(-0.5f * dpos) + EPS_F) + 1.0f;
        atomicAdd(&g_pos, (double)sp);
    }
}

// ---------------------------------------------------------------------------
// pair kernel: bf16 mma.sync Gram + exp + reduce over triangular tiles.
// grid = NPAIR (1D), 128 threads = 4 warps (2x2). CTA 128x128, warp 64x64.
// 3-stage cp.async pipeline, BK=32.
// ---------------------------------------------------------------------------
extern __shared__ __align__(16) __nv_bfloat16 smem_tiles[];

__global__ void __launch_bounds__(128, 2) pair_kernel() {
    __shared__ float s_sq[256];
    __shared__ float red[4];

    int tid = threadIdx.x;
    int lane = tid & 31;
    int wid = tid >> 5;
    int wm = wid & 1;    // m offset wm*64
    int wn = wid >> 1;   // n offset wn*64

    // linear index -> (ti, tj), tj >= ti  (row ti holds NT - ti tiles)
    int rem = blockIdx.x;
    int ti = 0;
    while (rem >= NT - ti) { rem -= NT - ti; ++ti; }
    int tj = ti + rem;

    const __nv_bfloat16* gA = g_z1nb + (size_t)ti * BM * DIMS;
    const __nv_bfloat16* gB = g_z1nb + (size_t)tj * BM * DIMS;

    // stage sq for the epilogue
    s_sq[tid]       = g_sq[ti * BM + tid];
    s_sq[128 + tid] = g_sq[tj * BM + tid];

    float acc[4][8][4];
    #pragma unroll
    for (int mt = 0; mt < 4; ++mt)
        #pragma unroll
        for (int nt = 0; nt < 8; ++nt)
            #pragma unroll
            for (int r = 0; r < 4; ++r)
                acc[mt][nt][r] = 0.f;

    auto issue = [&](int stage, int c) {
        __nv_bfloat16* base = smem_tiles + stage * STAGE_ELEMS;
        #pragma unroll
        for (int v = 0; v < 8; ++v) {
            int id   = tid + (v << 7);     // 0..1023 16B slots
            int m    = id >> 9;            // 0 = A, 1 = B
            int r    = (id >> 2) & 127;
            int atom = id & 3;
            unsigned dst = (unsigned)__cvta_generic_to_shared(
                base + m * (BM * BK) + swz(r, atom));
            const __nv_bfloat16* src =
                (m ? gB : gA) + r * DIMS + c * BK + (atom << 3);
            asm volatile("cp.async.cg.shared.global [%0], [%1], 16;\n"
                         :: "r"(dst), "l"(src));
        }
        asm volatile("cp.async.commit_group;\n");
    };

    issue(0, 0);
    issue(1, 1);

    int sel = lane >> 3;   // ldmatrix quadrant
    int l7  = lane & 7;

    for (int c = 0; c < NCHUNK; ++c) {
        if (c == NCHUNK - 1) asm volatile("cp.async.wait_group 0;\n");
        else                 asm volatile("cp.async.wait_group 1;\n");
        __syncthreads();
        if (c + 2 < NCHUNK) issue((c + 2) % NSTAGE, c + 2);

        const __nv_bfloat16* As = smem_tiles + (c % NSTAGE) * STAGE_ELEMS;
        const __nv_bfloat16* Bs = As + BM * BK;

        #pragma unroll
        for (int kk = 0; kk < BK; kk += 16) {
            unsigned af[4][4];
            unsigned bf_[8][2];

            #pragma unroll
            for (int mt = 0; mt < 4; ++mt) {
                int row  = wm * 64 + mt * 16 + ((sel & 1) << 3) + l7;
                int atom = (kk >> 3) + (sel >> 1);
                unsigned ad = (unsigned)__cvta_generic_to_shared(
                    &As[swz(row, atom)]);
                asm volatile(
                    "ldmatrix.sync.aligned.m8n8.x4.shared.b16 "
                    "{%0,%1,%2,%3}, [%4];\n"
                    : "=r"(af[mt][0]), "=r"(af[mt][1]),
                      "=r"(af[mt][2]), "=r"(af[mt][3])
                    : "r"(ad));
            }
            #pragma unroll
            for (int np = 0; np < 4; ++np) {
                int row  = wn * 64 + np * 16 + ((sel >> 1) << 3) + l7;
                int atom = (kk >> 3) + (sel & 1);
                unsigned bd = (unsigned)__cvta_generic_to_shared(
                    &Bs[swz(row, atom)]);
                asm volatile(
                    "ldmatrix.sync.aligned.m8n8.x4.shared.b16 "
                    "{%0,%1,%2,%3}, [%4];\n"
                    : "=r"(bf_[2 * np][0]), "=r"(bf_[2 * np][1]),
                      "=r"(bf_[2 * np + 1][0]), "=r"(bf_[2 * np + 1][1])
                    : "r"(bd));
            }

            #pragma unroll
            for (int mt = 0; mt < 4; ++mt)
                #pragma unroll
                for (int nt = 0; nt < 8; ++nt)
                    asm volatile(
                        "mma.sync.aligned.m16n8k16.row.col.f32.bf16.bf16.f32 "
                        "{%0,%1,%2,%3}, {%4,%5,%6,%7}, {%8,%9}, {%0,%1,%2,%3};\n"
                        : "+f"(acc[mt][nt][0]), "+f"(acc[mt][nt][1]),
                          "+f"(acc[mt][nt][2]), "+f"(acc[mt][nt][3])
                        : "r"(af[mt][0]), "r"(af[mt][1]),
                          "r"(af[mt][2]), "r"(af[mt][3]),
                          "r"(bf_[nt][0]), "r"(bf_[nt][1]));
        }
        __syncthreads();
    }

    // epilogue: d2 = max(sq_i + sq_j - 2*dot, 0); e = exp(-0.5*d2); mask diag
    int grow  = lane >> 2;
    int gcol2 = (lane & 3) << 1;
    float sum = 0.f;
    #pragma unroll
    for (int mt = 0; mt < 4; ++mt) {
        #pragma unroll
        for (int nt = 0; nt < 8; ++nt) {
            #pragma unroll
            for (int r = 0; r < 4; ++r) {
                int li = wm * 64 + mt * 16 + grow + ((r & 2) ? 8 : 0);
                int lj = wn * 64 + nt * 8 + gcol2 + (r & 1);
                float d2 = fmaxf(s_sq[li] + s_sq[128 + lj]
                                 - 2.0f * acc[mt][nt][r], 0.0f);
                float e = __expf(-0.5f * d2);
                if (ti == tj && li == lj) e = 0.f;   // diagonal mask
                sum += e;
            }
        }
    }

    // block reduce + single atomic per CTA
    #pragma unroll
    for (int o = 16; o > 0; o >>= 1)
        sum += __shfl_xor_sync(0xffffffffu, sum, o);
    if (lane == 0) red[wid] = sum;
    __syncthreads();
    if (tid == 0) {
        float s = red[0] + red[1] + red[2] + red[3];
        double contrib = (double)s;
        if (ti != tj) contrib *= 2.0;   // symmetric counterpart
        atomicAdd(&g_neg, contrib);
    }
}

// ---------------------------------------------------------------------------
__global__ void finalize_kernel(float* __restrict__ out) {
    if (threadIdx.x == 0) {
        double n = (double)NROWS;
        double mean_star = g_neg / (n * (n - 1.0)) + 1e-8;
        out[0] = (float)(-(g_pos / n) + 1.5 * mean_star);
    }
}

// ---------------------------------------------------------------------------
extern "C" void kernel_launch(void* const* d_in, const int* in_sizes, int n_in,
                              void* d_out, int out_size) {
    const float* z1 = (const float*)d_in[0];
    const float* z2 = (const float*)d_in[1];
    float* out = (float*)d_out;

    cudaFuncSetAttribute(pair_kernel,
                         cudaFuncAttributeMaxDynamicSharedMemorySize,
                         SMEM_BYTES);

    zero_kernel<<<1, 1>>>();
    prep_kernel<<<NROWS, 256>>>(z1, z2);
    pair_kernel<<<NPAIR, 128, SMEM_BYTES>>>();
    finalize_kernel<<<1, 32>>>(out);
}

// round 12
// speedup vs baseline: 1.1740x; 1.1740x over previous
#include <cuda_runtime.h>
#include <cuda_bf16.h>
#include <math.h>
#include <stdint.h>

// Problem constants
#define NROWS 8192
#define DIMS  256
#define NT    64                     // 8192 / 128 tiles per side
#define NPAIR (NT * (NT + 1) / 2)    // 2080 upper-triangular tiles
#define EPS_F 1e-8f

// Tiling: CTA 128x128, 8 warps (2x4), warp tile 64x32. BK=64 (128B rows).
#define BM 128
#define BK 64
#define NCHUNK (DIMS / BK)           // 4
#define NSTAGE 3
#define STAGE_ELEMS (2 * BM * BK)    // A + B per stage, bf16 elems (16384)
#define SMEM_BYTES (NSTAGE * STAGE_ELEMS * 2)   // 98304

// Scratch (static device globals: allocation-free)
__device__ __nv_bfloat16 g_z1nb[NROWS * DIMS];  // normalized z1, row-major bf16
__device__ float  g_sq[NROWS];                  // fp32 |row|^2 after normalize
__device__ double g_pos;                        // sum of s_pos
__device__ double g_neg;                        // off-diagonal exp-sum

// ---------------------------------------------------------------------------
// helpers
// ---------------------------------------------------------------------------
__device__ __forceinline__ float block_sum_256(float v, float* sbuf) {
    #pragma unroll
    for (int o = 16; o > 0; o >>= 1)
        v += __shfl_xor_sync(0xffffffffu, v, o);
    int w = threadIdx.x >> 5;
    if ((threadIdx.x & 31) == 0) sbuf[w] = v;
    __syncthreads();
    float s = 0.f;
    #pragma unroll
    for (int i = 0; i < 8; ++i) s += sbuf[i];
    __syncthreads();
    return s;
}

// SW128 swizzle on 128-byte rows (64 bf16): 16B atom a of row r -> a ^ (r&7).
// Conflict-free for ldmatrix 8-row phases and for cp.async 16B stores.
__device__ __forceinline__ int swz(int r, int a) {
    return r * 64 + ((a ^ (r & 7)) << 3);
}

// ---------------------------------------------------------------------------
__global__ void zero_kernel() { g_neg = 0.0; g_pos = 0.0; }

// ---------------------------------------------------------------------------
// prep: normalize rows, emit bf16 z1n (row-major), sq; accumulate s_pos sum
// grid = NROWS blocks, 256 threads (== DIMS)
// ---------------------------------------------------------------------------
__global__ void prep_kernel(const float* __restrict__ z1,
                            const float* __restrict__ z2) {
    __shared__ float sbuf[8];
    int i = blockIdx.x;
    int t = threadIdx.x;

    float a = z1[i * DIMS + t];
    float b = z2[i * DIMS + t];

    float s1 = block_sum_256(a * a, sbuf);
    float s2 = block_sum_256(b * b, sbuf);

    float m1 = fmaxf(sqrtf(s1), 1e-12f);
    float m2 = fmaxf(sqrtf(s2), 1e-12f);
    float an = a / m1;
    float bn = b / m2;

    g_z1nb[i * DIMS + t] = __float2bfloat16(an);

    float dpos = block_sum_256((an - bn) * (an - bn), sbuf);

    if (t == 0) {
        g_sq[i] = s1 / (m1 * m1);
        float sp = logf(__expf(-0.5f * dpos) + EPS_F) + 1.0f;
        atomicAdd(&g_pos, (double)sp);
    }
}

// ---------------------------------------------------------------------------
// pair kernel: bf16 mma.sync Gram + exp + reduce over triangular tiles.
// grid = NPAIR (1D), 256 threads = 8 warps (2x4), warp tile 64x32.
// 3-stage cp.async pipeline, BK=64, ONE __syncthreads per k-chunk.
// ---------------------------------------------------------------------------
extern __shared__ __align__(16) __nv_bfloat16 smem_tiles[];

__global__ void __launch_bounds__(256, 2) pair_kernel() {
    __shared__ float s_sq[256];
    __shared__ float red[8];

    int tid = threadIdx.x;
    int lane = tid & 31;
    int wid = tid >> 5;
    int wm = wid >> 2;   // 0..1 -> m offset wm*64
    int wn = wid & 3;    // 0..3 -> n offset wn*32

    // linear index -> (ti, tj), tj >= ti  (row ti holds NT - ti tiles)
    int rem = blockIdx.x;
    int ti = 0;
    while (rem >= NT - ti) { rem -= NT - ti; ++ti; }
    int tj = ti + rem;

    const __nv_bfloat16* gA = g_z1nb + (size_t)ti * BM * DIMS;
    const __nv_bfloat16* gB = g_z1nb + (size_t)tj * BM * DIMS;

    // stage sq for the epilogue
    if (tid < 128) s_sq[tid] = g_sq[ti * BM + tid];
    else           s_sq[tid] = g_sq[tj * BM + (tid - 128)];

    float acc[4][4][4];
    #pragma unroll
    for (int mt = 0; mt < 4; ++mt)
        #pragma unroll
        for (int nt = 0; nt < 4; ++nt)
            #pragma unroll
            for (int r = 0; r < 4; ++r)
                acc[mt][nt][r] = 0.f;

    auto issue = [&](int stage, int c) {
        __nv_bfloat16* base = smem_tiles + stage * STAGE_ELEMS;
        #pragma unroll
        for (int v = 0; v < 8; ++v) {
            int id = tid + (v << 8);       // 0..2047 16B slots
            int m  = id >> 10;             // 0 = A, 1 = B
            int r  = (id >> 3) & 127;
            int a  = id & 7;
            unsigned dst = (unsigned)__cvta_generic_to_shared(
                base + m * (BM * BK) + swz(r, a));
            const __nv_bfloat16* src =
                (m ? gB : gA) + r * DIMS + c * BK + (a << 3);
            asm volatile("cp.async.cg.shared.global [%0], [%1], 16;\n"
                         :: "r"(dst), "l"(src));
        }
        asm volatile("cp.async.commit_group;\n");
    };

    issue(0, 0);
    issue(1, 1);

    int sel = lane >> 3;   // ldmatrix quadrant
    int l7  = lane & 7;

    for (int c = 0; c < NCHUNK; ++c) {
        if (c == NCHUNK - 1) asm volatile("cp.async.wait_group 0;\n");
        else                 asm volatile("cp.async.wait_group 1;\n");
        __syncthreads();
        if (c + 2 < NCHUNK) issue((c + 2) % NSTAGE, c + 2);

        const __nv_bfloat16* As = smem_tiles + (c % NSTAGE) * STAGE_ELEMS;
        const __nv_bfloat16* Bs = As + BM * BK;

        #pragma unroll
        for (int kk = 0; kk < BK; kk += 16) {
            unsigned af[4][4];
            unsigned bf_[4][2];

            #pragma unroll
            for (int mt = 0; mt < 4; ++mt) {
                int row  = wm * 64 + mt * 16 + ((sel & 1) << 3) + l7;
                int atom = (kk >> 3) + (sel >> 1);
                unsigned ad = (unsigned)__cvta_generic_to_shared(
                    &As[swz(row, atom)]);
                asm volatile(
                    "ldmatrix.sync.aligned.m8n8.x4.shared.b16 "
                    "{%0,%1,%2,%3}, [%4];\n"
                    : "=r"(af[mt][0]), "=r"(af[mt][1]),
                      "=r"(af[mt][2]), "=r"(af[mt][3])
                    : "r"(ad));
            }
            #pragma unroll
            for (int np = 0; np < 2; ++np) {
                int row  = wn * 32 + np * 16 + ((sel >> 1) << 3) + l7;
                int atom = (kk >> 3) + (sel & 1);
                unsigned bd = (unsigned)__cvta_generic_to_shared(
                    &Bs[swz(row, atom)]);
                asm volatile(
                    "ldmatrix.sync.aligned.m8n8.x4.shared.b16 "
                    "{%0,%1,%2,%3}, [%4];\n"
                    : "=r"(bf_[2 * np][0]), "=r"(bf_[2 * np][1]),
                      "=r"(bf_[2 * np + 1][0]), "=r"(bf_[2 * np + 1][1])
                    : "r"(bd));
            }

            #pragma unroll
            for (int mt = 0; mt < 4; ++mt)
                #pragma unroll
                for (int nt = 0; nt < 4; ++nt)
                    asm volatile(
                        "mma.sync.aligned.m16n8k16.row.col.f32.bf16.bf16.f32 "
                        "{%0,%1,%2,%3}, {%4,%5,%6,%7}, {%8,%9}, {%0,%1,%2,%3};\n"
                        : "+f"(acc[mt][nt][0]), "+f"(acc[mt][nt][1]),
                          "+f"(acc[mt][nt][2]), "+f"(acc[mt][nt][3])
                        : "r"(af[mt][0]), "r"(af[mt][1]),
                          "r"(af[mt][2]), "r"(af[mt][3]),
                          "r"(bf_[nt][0]), "r"(bf_[nt][1]));
        }
        __syncthreads();
    }

    // epilogue: d2 = max(sq_i + sq_j - 2*dot, 0); e = exp(-0.5*d2); mask diag
    int grow  = lane >> 2;
    int gcol2 = (lane & 3) << 1;
    float sum = 0.f;
    #pragma unroll
    for (int mt = 0; mt < 4; ++mt) {
        #pragma unroll
        for (int nt = 0; nt < 4; ++nt) {
            #pragma unroll
            for (int r = 0; r < 4; ++r) {
                int li = wm * 64 + mt * 16 + grow + ((r & 2) ? 8 : 0);
                int lj = wn * 32 + nt * 8 + gcol2 + (r & 1);
                float d2 = fmaxf(s_sq[li] + s_sq[128 + lj]
                                 - 2.0f * acc[mt][nt][r], 0.0f);
                float e = __expf(-0.5f * d2);
                if (ti == tj && li == lj) e = 0.f;   // diagonal mask
                sum += e;
            }
        }
    }

    // block reduce + single atomic per CTA
    #pragma unroll
    for (int o = 16; o > 0; o >>= 1)
        sum += __shfl_xor_sync(0xffffffffu, sum, o);
    if (lane == 0) red[wid] = sum;
    __syncthreads();
    if (tid == 0) {
        float s = 0.f;
        #pragma unroll
        for (int w = 0; w < 8; ++w) s += red[w];
        double contrib = (double)s;
        if (ti != tj) contrib *= 2.0;   // symmetric counterpart
        atomicAdd(&g_neg, contrib);
    }
}

// ---------------------------------------------------------------------------
__global__ void finalize_kernel(float* __restrict__ out) {
    if (threadIdx.x == 0) {
        double n = (double)NROWS;
        double mean_star = g_neg / (n * (n - 1.0)) + 1e-8;
        out[0] = (float)(-(g_pos / n) + 1.5 * mean_star);
    }
}

// ---------------------------------------------------------------------------
extern "C" void kernel_launch(void* const* d_in, const int* in_sizes, int n_in,
                              void* d_out, int out_size) {
    const float* z1 = (const float*)d_in[0];
    const float* z2 = (const float*)d_in[1];
    float* out = (float*)d_out;

    cudaFuncSetAttribute(pair_kernel,
                         cudaFuncAttributeMaxDynamicSharedMemorySize,
                         SMEM_BYTES);

    zero_kernel<<<1, 1>>>();
    prep_kernel<<<NROWS, 256>>>(z1, z2);
    pair_kernel<<<NPAIR, 256, SMEM_BYTES>>>();
    finalize_kernel<<<1, 32>>>(out);
}

// round 13
// speedup vs baseline: 1.2417x; 1.0577x over previous
#include <cuda_runtime.h>
#include <cuda_bf16.h>
#include <math.h>
#include <stdint.h>

// Problem constants
#define NROWS 8192
#define DIMS  256
#define NT    64                     // 8192 / 128 tiles per side
#define NPAIR (NT * (NT + 1) / 2)    // 2080 upper-triangular tiles
#define EPS_F 1e-8f

// Tiling (validated R3 config): CTA 128x128, 8 warps (2x4), warp 64x32, BK=32
#define BM 128
#define BK 32

// Scratch (static device globals: allocation-free)
__device__ __nv_bfloat16 g_z1nb[NROWS * DIMS];  // normalized z1, row-major bf16
__device__ float  g_sq[NROWS];                  // fp32 |row|^2 after normalize
__device__ float  g_spos[NROWS];                // per-row positive-pair score
__device__ double g_partial[NPAIR];             // per-tile weighted exp sums
__device__ int    g_count = 0;                  // completion counter (self-resetting)

// ---------------------------------------------------------------------------
// helpers
// ---------------------------------------------------------------------------
__device__ __forceinline__ float block_sum_256(float v, float* sbuf) {
    #pragma unroll
    for (int o = 16; o > 0; o >>= 1)
        v += __shfl_xor_sync(0xffffffffu, v, o);
    int w = threadIdx.x >> 5;
    if ((threadIdx.x & 31) == 0) sbuf[w] = v;
    __syncthreads();
    float s = 0.f;
    #pragma unroll
    for (int i = 0; i < 8; ++i) s += sbuf[i];
    __syncthreads();
    return s;
}

// SMEM tile layout: row-major 128 x 32 bf16 (64B rows), XOR swizzle on 16B
// atoms; conflict-free for ldmatrix 8-row phases and cp.async 16B stores.
__device__ __forceinline__ int swz(int r, int atom) {
    return r * 32 + ((atom ^ ((r >> 1) & 3)) << 3);
}

// ---------------------------------------------------------------------------
// prep: normalize rows, emit bf16 z1n (row-major), sq, s_pos (plain stores)
// grid = NROWS blocks, 256 threads (== DIMS)
// ---------------------------------------------------------------------------
__global__ void prep_kernel(const float* __restrict__ z1,
                            const float* __restrict__ z2) {
    __shared__ float sbuf[8];
    int i = blockIdx.x;
    int t = threadIdx.x;

    float a = z1[i * DIMS + t];
    float b = z2[i * DIMS + t];

    float s1 = block_sum_256(a * a, sbuf);
    float s2 = block_sum_256(b * b, sbuf);

    float m1 = fmaxf(sqrtf(s1), 1e-12f);
    float m2 = fmaxf(sqrtf(s2), 1e-12f);
    float an = a / m1;
    float bn = b / m2;

    g_z1nb[i * DIMS + t] = __float2bfloat16(an);

    float dpos = block_sum_256((an - bn) * (an - bn), sbuf);

    if (t == 0) {
        g_sq[i] = s1 / (m1 * m1);
        g_spos[i] = logf(__expf(-0.5f * dpos) + EPS_F) + 1.0f;
    }
}

// ---------------------------------------------------------------------------
// pair kernel: bf16 mma.sync Gram + exp + reduce (R3-validated core) with
// fused last-CTA finalize. grid = (64, 64), 256 threads = 8 warps (2x4).
// ---------------------------------------------------------------------------
__global__ void __launch_bounds__(256, 2) pair_kernel(float* __restrict__ out) {
    int ti = blockIdx.y;
    int tj = blockIdx.x;
    if (tj < ti) return;   // uniform per-CTA

    __shared__ __align__(16) __nv_bfloat16 As[2][BM * BK];
    __shared__ __align__(16) __nv_bfloat16 Bs[2][BM * BK];
    __shared__ float s_sq[256];
    __shared__ float red[8];
    __shared__ int s_last;

    int tid = threadIdx.x;
    int lane = tid & 31;
    int wid = tid >> 5;
    int wm = wid >> 2;   // 0..1 -> m offset wm*64
    int wn = wid & 3;    // 0..3 -> n offset wn*32

    const __nv_bfloat16* gA = g_z1nb + (size_t)ti * BM * DIMS;
    const __nv_bfloat16* gB = g_z1nb + (size_t)tj * BM * DIMS;

    // stage sq values for the epilogue
    if (tid < 128) s_sq[tid] = g_sq[ti * BM + tid];
    else           s_sq[tid] = g_sq[tj * BM + (tid - 128)];

    float acc[4][4][4];
    #pragma unroll
    for (int mt = 0; mt < 4; ++mt)
        #pragma unroll
        for (int nt = 0; nt < 4; ++nt)
            #pragma unroll
            for (int r = 0; r < 4; ++r)
                acc[mt][nt][r] = 0.f;

    auto issue = [&](int buf, int kt) {
        #pragma unroll
        for (int s = 0; s < 2; ++s) {
            int idx  = tid + (s << 8);      // 0..511
            int r    = idx >> 2;            // 0..127
            int atom = idx & 3;             // 0..3
            int off  = swz(r, atom);
            unsigned da = (unsigned)__cvta_generic_to_shared(&As[buf][off]);
            unsigned db = (unsigned)__cvta_generic_to_shared(&Bs[buf][off]);
            const __nv_bfloat16* sa = gA + r * DIMS + kt * BK + (atom << 3);
            const __nv_bfloat16* sb = gB + r * DIMS + kt * BK + (atom << 3);
            asm volatile("cp.async.cg.shared.global [%0], [%1], 16;\n"
                         :: "r"(da), "l"(sa));
            asm volatile("cp.async.cg.shared.global [%0], [%1], 16;\n"
                         :: "r"(db), "l"(sb));
        }
        asm volatile("cp.async.commit_group;\n");
    };

    issue(0, 0);

    int sel = lane >> 3;   // ldmatrix quadrant
    int l7  = lane & 7;

    for (int kt = 0; kt < DIMS / BK; ++kt) {
        int buf = kt & 1;
        if (kt < DIMS / BK - 1) {
            issue(buf ^ 1, kt + 1);
            asm volatile("cp.async.wait_group 1;\n");
        } else {
            asm volatile("cp.async.wait_group 0;\n");
        }
        __syncthreads();

        #pragma unroll
        for (int kk = 0; kk < BK; kk += 16) {
            unsigned af[4][4];
            unsigned bf_[4][2];

            #pragma unroll
            for (int mt = 0; mt < 4; ++mt) {
                int row  = wm * 64 + mt * 16 + ((sel & 1) << 3) + l7;
                int atom = (kk >> 3) + (sel >> 1);
                unsigned ad = (unsigned)__cvta_generic_to_shared(
                    &As[buf][swz(row, atom)]);
                asm volatile(
                    "ldmatrix.sync.aligned.m8n8.x4.shared.b16 "
                    "{%0,%1,%2,%3}, [%4];\n"
                    : "=r"(af[mt][0]), "=r"(af[mt][1]),
                      "=r"(af[mt][2]), "=r"(af[mt][3])
                    : "r"(ad));
            }
            #pragma unroll
            for (int np = 0; np < 2; ++np) {
                int row  = wn * 32 + np * 16 + ((sel >> 1) << 3) + l7;
                int atom = (kk >> 3) + (sel & 1);
                unsigned bd = (unsigned)__cvta_generic_to_shared(
                    &Bs[buf][swz(row, atom)]);
                asm volatile(
                    "ldmatrix.sync.aligned.m8n8.x4.shared.b16 "
                    "{%0,%1,%2,%3}, [%4];\n"
                    : "=r"(bf_[2 * np][0]), "=r"(bf_[2 * np][1]),
                      "=r"(bf_[2 * np + 1][0]), "=r"(bf_[2 * np + 1][1])
                    : "r"(bd));
            }

            #pragma unroll
            for (int mt = 0; mt < 4; ++mt)
                #pragma unroll
                for (int nt = 0; nt < 4; ++nt)
                    asm volatile(
                        "mma.sync.aligned.m16n8k16.row.col.f32.bf16.bf16.f32 "
                        "{%0,%1,%2,%3}, {%4,%5,%6,%7}, {%8,%9}, {%0,%1,%2,%3};\n"
                        : "+f"(acc[mt][nt][0]), "+f"(acc[mt][nt][1]),
                          "+f"(acc[mt][nt][2]), "+f"(acc[mt][nt][3])
                        : "r"(af[mt][0]), "r"(af[mt][1]),
                          "r"(af[mt][2]), "r"(af[mt][3]),
                          "r"(bf_[nt][0]), "r"(bf_[nt][1]));
        }
        __syncthreads();
    }

    // epilogue: d2 = max(sq_i + sq_j - 2*dot, 0); e = exp(-0.5*d2); mask diag
    int grow  = lane >> 2;
    int gcol2 = (lane & 3) << 1;
    float sum = 0.f;
    #pragma unroll
    for (int mt = 0; mt < 4; ++mt) {
        #pragma unroll
        for (int nt = 0; nt < 4; ++nt) {
            #pragma unroll
            for (int r = 0; r < 4; ++r) {
                int li = wm * 64 + mt * 16 + grow + ((r & 2) ? 8 : 0);
                int lj = wn * 32 + nt * 8 + gcol2 + (r & 1);
                float d2 = fmaxf(s_sq[li] + s_sq[128 + lj]
                                 - 2.0f * acc[mt][nt][r], 0.0f);
                float e = __expf(-0.5f * d2);
                if (ti * BM + li == tj * BM + lj) e = 0.f;   // diagonal mask
                sum += e;
            }
        }
    }

    // block reduce -> one partial store per CTA (x2 weight for off-diagonal)
    #pragma unroll
    for (int o = 16; o > 0; o >>= 1)
        sum += __shfl_xor_sync(0xffffffffu, sum, o);
    if (lane == 0) red[wid] = sum;
    __syncthreads();

    // linear triangular slot for this (ti, tj)
    int slot = ti * NT - (ti * (ti - 1)) / 2 + (tj - ti);

    if (tid == 0) {
        float s = 0.f;
        #pragma unroll
        for (int w = 0; w < 8; ++w) s += red[w];
        double contrib = (double)s;
        if (ti != tj) contrib *= 2.0;
        g_partial[slot] = contrib;
        __threadfence();
        int t = atomicAdd(&g_count, 1);
        s_last = (t == NPAIR - 1);
    }
    __syncthreads();

    // last CTA: fused finalize
    if (s_last) {
        __threadfence();
        if (tid == 0) g_count = 0;   // reset for next graph replay

        // sum partials in double
        double dneg = 0.0;
        for (int i = tid; i < NPAIR; i += 256) dneg += g_partial[i];
        #pragma unroll
        for (int o = 16; o > 0; o >>= 1)
            dneg += __shfl_xor_sync(0xffffffffu, dneg, o);
        __shared__ double dred[8];
        if (lane == 0) dred[wid] = dneg;

        // sum spos in float tree
        float ps = 0.f;
        for (int i = tid; i < NROWS; i += 256) ps += g_spos[i];
        #pragma unroll
        for (int o = 16; o > 0; o >>= 1)
            ps += __shfl_xor_sync(0xffffffffu, ps, o);
        __shared__ float fred[8];
        if (lane == 0) fred[wid] = ps;
        __syncthreads();

        if (tid == 0) {
            double neg = 0.0;
            float pos = 0.f;
            #pragma unroll
            for (int w = 0; w < 8; ++w) { neg += dred[w]; pos += fred[w]; }
            double n = (double)NROWS;
            double mean_star = neg / (n * (n - 1.0)) + 1e-8;
            out[0] = (float)(-((double)pos / n) + 1.5 * mean_star);
        }
    }
}

// ---------------------------------------------------------------------------
extern "C" void kernel_launch(void* const* d_in, const int* in_sizes, int n_in,
                              void* d_out, int out_size) {
    const float* z1 = (const float*)d_in[0];
    const float* z2 = (const float*)d_in[1];
    float* out = (float*)d_out;

    prep_kernel<<<NROWS, 256>>>(z1, z2);
    dim3 grid(NT, NT);
    pair_kernel<<<grid, 256>>>(out);
}